// round 14
// baseline (speedup 1.0000x reference)
#include <cuda_runtime.h>
#include <math.h>

#define EPSV 1e-5f

typedef unsigned long long u64;

__device__ __forceinline__ u64 fma2(u64 a, u64 b, u64 c) {
    u64 d; asm("fma.rn.f32x2 %0, %1, %2, %3;" : "=l"(d) : "l"(a), "l"(b), "l"(c)); return d;
}
__device__ __forceinline__ u64 pack2(float lo, float hi) {
    u64 r; asm("mov.b64 %0, {%1, %2};" : "=l"(r) : "f"(lo), "f"(hi)); return r;
}
__device__ __forceinline__ void unpack2(u64 v, float& lo, float& hi) {
    asm("mov.b64 {%0, %1}, %2;" : "=f"(lo), "=f"(hi) : "l"(v));
}

// ---------------- scratch (no cudaMalloc allowed) ----------------
__device__ float g_h1[4 * 64 * 64 * 128];       // conv1 out, NHWC
__device__ float g_h2[4 * 64 * 64 * 256];       // conv2 out, NHWC
__device__ float g_w2t[256 * 9 * 128];          // c2w transposed [oc][r][ic]
__device__ float g_w3t[256 * 4 * 256];          // pw  transposed [oc][r][ic]
__device__ float g_s[4 * 1024 * 256];           // sequence
__device__ float g_xr[4 * 1024 * 1024];         // in_proj out (xi | res)
__device__ float g_xl[4 * 1024 * 512];          // after dw conv
__device__ float g_xdbl[4 * 1024 * 64];         // x_proj out (dt|B|C)
__device__ float g_delta[4 * 1024 * 512];
__device__ float g_y[4 * 1024 * 512];           // scan out * silu(res)
__device__ float g_y2[4 * 1024 * 256];          // out_proj out
__device__ float g_poolp[4 * 16 * 256];         // partial pool sums
__device__ float g_pool[4 * 256];

__device__ __forceinline__ float gelu_f(float x) {
    return 0.5f * x * (1.f + erff(x * 0.70710678118654752f));
}

// ---------------- fused: conv1 (NHWC out) + both weight transposes (round-10) -------
__global__ void stem_pre_kernel(const float* __restrict__ x, const float* __restrict__ w,
                                const float* __restrict__ cb, const float* __restrict__ g,
                                const float* __restrict__ bb,
                                const float* __restrict__ c2w, const float* __restrict__ pw) {
    int bid = blockIdx.x;
    if (bid < 8192) {
        int idx = bid * 256 + threadIdx.x;
        int oc = idx & 127;
        int xo = (idx >> 7) & 63;
        int yo = (idx >> 13) & 63;
        int b  = idx >> 19;
        float acc = cb[oc];
        #pragma unroll
        for (int ic = 0; ic < 3; ic++) {
            #pragma unroll
            for (int ky = 0; ky < 3; ky++) {
                int iy = yo + ky - 1;
                if (iy < 0 || iy > 63) continue;
                #pragma unroll
                for (int kx = 0; kx < 3; kx++) {
                    int ix = xo + kx - 1;
                    if (ix < 0 || ix > 63) continue;
                    acc = fmaf(x[((b * 3 + ic) * 64 + iy) * 64 + ix],
                               w[((oc * 3 + ic) * 3 + ky) * 3 + kx], acc);
                }
            }
        }
        acc = acc * (g[oc] * rsqrtf(1.f + EPSV)) + bb[oc];
        g_h1[idx] = gelu_f(acc);
    } else if (bid < 8192 + 1152) {
        int idx = (bid - 8192) * 256 + threadIdx.x;
        int oc = idx / 1152;
        int rem = idx % 1152;
        int r = rem >> 7;
        int ic = rem & 127;
        g_w2t[idx] = c2w[(oc * 128 + ic) * 9 + r];
    } else {
        int idx = (bid - 9344) * 256 + threadIdx.x;
        int oc = idx >> 10;
        int rem = idx & 1023;
        int r = rem >> 8;
        int ic = rem & 255;
        g_w3t[idx] = pw[(oc * 256 + ic) * 4 + r];
    }
}

// ---------------- A-fragment gather for implicit-GEMM modes ----------------
template <int MODE>
__device__ __forceinline__ float4 gatherA(const float* __restrict__ src, int lda,
                                          int row, int k) {
    if (MODE == 0) {
        return *(const float4*)(src + (size_t)row * lda + k);
    } else if (MODE == 1) {
        int b = row >> 12, y = (row >> 6) & 63, x = row & 63;
        int r = k >> 7, ic = k & 127;
        int ky = (r * 11) >> 5;
        int kx = r - 3 * ky;
        int iy = y + ky - 1, ix = x + kx - 1;
        if (iy < 0 || iy > 63 || ix < 0 || ix > 63) return make_float4(0.f, 0.f, 0.f, 0.f);
        return *(const float4*)(src + ((((b << 6) + iy) << 6) + ix) * 128 + ic);
    } else {
        int b = row >> 10, oy = (row >> 5) & 31, ox = row & 31;
        int r = k >> 8, ic = k & 255;
        int iy = 2 * oy + (r >> 1), ix = 2 * ox + (r & 1);
        return *(const float4*)(src + ((((b << 6) + iy) << 6) + ix) * 256 + ic);
    }
}

// ------- warp-tiled SGEMM, BK=16: duplicated-A smem + u64 pair loads + FFMA2 -------
// C[M,N] = A[M,K] @ W[N,K]^T (+bias, epilogue).  act: 0 none, 1 softplus, 2 BN+GELU
template <int BM, int BN, int MODE>
__global__ void __launch_bounds__(256, 2)
gemm7_kernel(const float* __restrict__ A, int lda,
             const float* __restrict__ W,
             const float* __restrict__ bias,
             const float* __restrict__ bng,
             const float* __restrict__ bnb,
             float* __restrict__ C, int ldc,
             int K, int act) {
    constexpr int BK = 16;
    constexpr int TM = BM / 16;
    constexpr int TN = BN / 16;
    constexpr int QM = TM / 4;
    constexpr int QN = TN / 4;
    constexpr int TN2 = TN / 2;
    constexpr int AV = BM / 64;          // float4 loads per thread for A (2 or 1)
    constexpr int WV = BN / 64;          // float4 loads per thread for W (2 or 1)
    __shared__ __align__(16) float Asd[2][BK][2 * BM];
    __shared__ __align__(16) float Ws[2][BK][BN];
    int tid = threadIdx.x;
    int wid = tid >> 5, lane = tid & 31;
    int wm = wid >> 2, wn = wid & 3;
    int lm = lane >> 2, ln = lane & 3;
    int bm = blockIdx.y * BM, bn = blockIdx.x * BN;

    // A loader indices
    int aRow = (AV == 2) ? (tid >> 1) : (tid >> 2);
    int aK   = (AV == 2) ? ((tid & 1) * 8) : ((tid & 3) * 4);
    int aGRow = bm + aRow;
    // W loader indices
    int wRow = (WV == 2) ? (tid >> 1) : (tid >> 2);
    int wK   = (WV == 2) ? ((tid & 1) * 8) : ((tid & 3) * 4);
    const float* Wp = W + (size_t)(bn + wRow) * K + wK;

    float4 av[2], wv[2];
    #pragma unroll
    for (int v = 0; v < AV; v++) av[v] = gatherA<MODE>(A, lda, aGRow, aK + v * 4);
    #pragma unroll
    for (int v = 0; v < WV; v++) wv[v] = *(const float4*)(Wp + v * 4);
    #pragma unroll
    for (int v = 0; v < AV; v++) {
        const float* f = (const float*)&av[v];
        #pragma unroll
        for (int j = 0; j < 4; j++)
            *(float2*)&Asd[0][aK + v * 4 + j][2 * aRow] = make_float2(f[j], f[j]);
    }
    #pragma unroll
    for (int v = 0; v < WV; v++) {
        const float* f = (const float*)&wv[v];
        #pragma unroll
        for (int j = 0; j < 4; j++)
            Ws[0][wK + v * 4 + j][wRow] = f[j];
    }
    __syncthreads();

    u64 acc2[TM][TN2];
    #pragma unroll
    for (int i = 0; i < TM; i++)
        #pragma unroll
        for (int j = 0; j < TN2; j++) acc2[i][j] = pack2(0.f, 0.f);

    int nT = K / BK;
    for (int t = 0; t < nT; t++) {
        int buf = t & 1;
        if (t + 1 < nT) {
            #pragma unroll
            for (int v = 0; v < AV; v++)
                av[v] = gatherA<MODE>(A, lda, aGRow, (t + 1) * BK + aK + v * 4);
            #pragma unroll
            for (int v = 0; v < WV; v++)
                wv[v] = *(const float4*)(Wp + (t + 1) * BK + v * 4);
        }
        #pragma unroll
        for (int kk = 0; kk < BK; kk++) {
            u64 a2[TM], bp[TN2];
            #pragma unroll
            for (int q = 0; q < QM; q++)
                #pragma unroll
                for (int ii = 0; ii < 4; ii++)
                    a2[q * 4 + ii] = *(const u64*)
                        &Asd[buf][kk][2 * (wm * (BM / 2) + q * (BM / 4) + lm * 4 + ii)];
            #pragma unroll
            for (int q = 0; q < QN; q++)
                #pragma unroll
                for (int jj = 0; jj < 2; jj++)
                    bp[q * 2 + jj] = *(const u64*)
                        &Ws[buf][kk][wn * (BN / 4) + q * (BN / 8) + ln * 4 + 2 * jj];
            #pragma unroll
            for (int i = 0; i < TM; i++)
                #pragma unroll
                for (int j = 0; j < TN2; j++)
                    acc2[i][j] = fma2(a2[i], bp[j], acc2[i][j]);
        }
        if (t + 1 < nT) {
            int nb = buf ^ 1;
            #pragma unroll
            for (int v = 0; v < AV; v++) {
                const float* f = (const float*)&av[v];
                #pragma unroll
                for (int j = 0; j < 4; j++)
                    *(float2*)&Asd[nb][aK + v * 4 + j][2 * aRow] = make_float2(f[j], f[j]);
            }
            #pragma unroll
            for (int v = 0; v < WV; v++) {
                const float* f = (const float*)&wv[v];
                #pragma unroll
                for (int j = 0; j < 4; j++)
                    Ws[nb][wK + v * 4 + j][wRow] = f[j];
            }
            __syncthreads();
        }
    }

    float acc[TM][TN];
    #pragma unroll
    for (int i = 0; i < TM; i++)
        #pragma unroll
        for (int j = 0; j < TN2; j++)
            unpack2(acc2[i][j], acc[i][2 * j], acc[i][2 * j + 1]);

    #pragma unroll
    for (int qn = 0; qn < QN; qn++) {
        int n0 = bn + wn * (BN / 4) + qn * (BN / 8) + ln * 4;
        float bj[4], gj[4], bbj[4];
        #pragma unroll
        for (int j = 0; j < 4; j++) {
            bj[j] = bias ? bias[n0 + j] : 0.f;
            if (act == 2) {
                gj[j] = bng[n0 + j] * rsqrtf(1.f + EPSV);
                bbj[j] = bnb[n0 + j];
            }
        }
        #pragma unroll
        for (int qm = 0; qm < QM; qm++) {
            #pragma unroll
            for (int i = 0; i < 4; i++) {
                int m = bm + wm * (BM / 2) + qm * (BM / 4) + lm * 4 + i;
                float4 o;
                float* op = (float*)&o;
                #pragma unroll
                for (int j = 0; j < 4; j++) {
                    float v = acc[qm * 4 + i][qn * 4 + j] + bj[j];
                    if (act == 1) v = (v > 20.f) ? v : log1pf(expf(v));
                    else if (act == 2) v = gelu_f(v * gj[j] + bbj[j]);
                    op[j] = v;
                }
                *(float4*)&C[(size_t)m * ldc + n0] = o;
            }
        }
    }
}

// ---------------- depthwise conv1d K=4, pad (1,2), vectorized x4 channels ----------
__global__ void dwconv_kernel(const float* __restrict__ cw, const float* __restrict__ cb) {
    int idx = blockIdx.x * blockDim.x + threadIdx.x;
    if (idx >= 4 * 1024 * 128) return;
    int d4 = idx & 127;
    int d = d4 << 2;
    int l = (idx >> 7) & 1023;
    int b = idx >> 17;
    float4 acc = *(const float4*)&cb[d];
    float4 w0 = *(const float4*)&cw[(d + 0) * 4];
    float4 w1 = *(const float4*)&cw[(d + 1) * 4];
    float4 w2 = *(const float4*)&cw[(d + 2) * 4];
    float4 w3 = *(const float4*)&cw[(d + 3) * 4];
    const float* wp0 = (const float*)&w0;
    const float* wp1 = (const float*)&w1;
    const float* wp2 = (const float*)&w2;
    const float* wp3 = (const float*)&w3;
    #pragma unroll
    for (int k = 0; k < 4; k++) {
        int l2 = l - 1 + k;
        if (l2 >= 0 && l2 < 1024) {
            float4 xv = *(const float4*)&g_xr[(size_t)(b * 1024 + l2) * 1024 + d];
            acc.x = fmaf(wp0[k], xv.x, acc.x);
            acc.y = fmaf(wp1[k], xv.y, acc.y);
            acc.z = fmaf(wp2[k], xv.z, acc.z);
            acc.w = fmaf(wp3[k], xv.w, acc.w);
        }
    }
    *(float4*)&g_xl[(size_t)(b * 1024 + l) * 512 + d] = acc;
}

// --------- fused x_proj (64x64x512 GEMM) + dt_proj (K=32 GEMM) + softplus ----------
__global__ void __launch_bounds__(256, 2)
xdt_kernel(const float* __restrict__ xpw, const float* __restrict__ dpw,
           const float* __restrict__ dpb) {
    constexpr int BK = 8;
    __shared__ __align__(16) float Asd[2][BK][2 * 64];
    __shared__ __align__(16) float Ws[2][BK][64];
    __shared__ __align__(16) float sdt[64][36];
    int tid = threadIdx.x;
    int wid = tid >> 5, lane = tid & 31;
    int wm = wid >> 2, wn = wid & 3;
    int lm = lane >> 2, ln = lane & 3;
    int bm = blockIdx.y * 64;

    int aRow = tid >> 1;
    int aK = (tid & 1) * 4;
    bool act8 = aRow < 64;
    const float* Ap = g_xl + (size_t)(bm + (act8 ? aRow : 0)) * 512 + aK;
    const float* Wp = xpw + (size_t)(act8 ? aRow : 0) * 512 + aK;

    float4 av = make_float4(0, 0, 0, 0), wv = make_float4(0, 0, 0, 0);
    if (act8) { av = *(const float4*)Ap; wv = *(const float4*)Wp; }
    if (act8) {
        *(float2*)&Asd[0][aK + 0][2 * aRow] = make_float2(av.x, av.x);
        *(float2*)&Asd[0][aK + 1][2 * aRow] = make_float2(av.y, av.y);
        *(float2*)&Asd[0][aK + 2][2 * aRow] = make_float2(av.z, av.z);
        *(float2*)&Asd[0][aK + 3][2 * aRow] = make_float2(av.w, av.w);
        Ws[0][aK + 0][aRow] = wv.x; Ws[0][aK + 1][aRow] = wv.y;
        Ws[0][aK + 2][aRow] = wv.z; Ws[0][aK + 3][aRow] = wv.w;
    }
    __syncthreads();

    u64 acc2[4][2];
    #pragma unroll
    for (int i = 0; i < 4; i++)
        #pragma unroll
        for (int j = 0; j < 2; j++) acc2[i][j] = pack2(0.f, 0.f);

    for (int t = 0; t < 64; t++) {
        int buf = t & 1;
        if (t + 1 < 64 && act8) {
            av = *(const float4*)(Ap + (t + 1) * BK);
            wv = *(const float4*)(Wp + (t + 1) * BK);
        }
        #pragma unroll
        for (int kk = 0; kk < BK; kk++) {
            u64 a2[4], bp[2];
            #pragma unroll
            for (int ii = 0; ii < 4; ii++)
                a2[ii] = *(const u64*)&Asd[buf][kk][2 * (wm * 32 + lm * 4 + ii)];
            #pragma unroll
            for (int jj = 0; jj < 2; jj++)
                bp[jj] = *(const u64*)&Ws[buf][kk][wn * 16 + ln * 4 + 2 * jj];
            #pragma unroll
            for (int i = 0; i < 4; i++)
                #pragma unroll
                for (int j = 0; j < 2; j++)
                    acc2[i][j] = fma2(a2[i], bp[j], acc2[i][j]);
        }
        if (t + 1 < 64 && act8) {
            int nb = buf ^ 1;
            *(float2*)&Asd[nb][aK + 0][2 * aRow] = make_float2(av.x, av.x);
            *(float2*)&Asd[nb][aK + 1][2 * aRow] = make_float2(av.y, av.y);
            *(float2*)&Asd[nb][aK + 2][2 * aRow] = make_float2(av.z, av.z);
            *(float2*)&Asd[nb][aK + 3][2 * aRow] = make_float2(av.w, av.w);
            Ws[nb][aK + 0][aRow] = wv.x; Ws[nb][aK + 1][aRow] = wv.y;
            Ws[nb][aK + 2][aRow] = wv.z; Ws[nb][aK + 3][aRow] = wv.w;
        }
        __syncthreads();
    }

    int n0 = wn * 16 + ln * 4;
    #pragma unroll
    for (int i = 0; i < 4; i++) {
        int m = wm * 32 + lm * 4 + i;
        float v0, v1, v2, v3;
        unpack2(acc2[i][0], v0, v1);
        unpack2(acc2[i][1], v2, v3);
        float4 o = make_float4(v0, v1, v2, v3);
        *(float4*)&g_xdbl[(size_t)(bm + m) * 64 + n0] = o;
        if (n0 < 32) {
            sdt[m][n0 + 0] = v0; sdt[m][n0 + 1] = v1;
            sdt[m][n0 + 2] = v2; sdt[m][n0 + 3] = v3;
        }
    }
    __syncthreads();

    int m = tid >> 2;
    int j0 = (tid & 3) * 4;
    for (int it = 0; it < 32; it++) {
        int j = j0 + it * 16;
        float a0 = dpb[j + 0], a1 = dpb[j + 1], a2v = dpb[j + 2], a3 = dpb[j + 3];
        #pragma unroll
        for (int k4 = 0; k4 < 8; k4++) {
            float4 sa = *(const float4*)&sdt[m][k4 * 4];
            float4 w0 = *(const float4*)&dpw[(j + 0) * 32 + k4 * 4];
            float4 w1 = *(const float4*)&dpw[(j + 1) * 32 + k4 * 4];
            float4 w2 = *(const float4*)&dpw[(j + 2) * 32 + k4 * 4];
            float4 w3 = *(const float4*)&dpw[(j + 3) * 32 + k4 * 4];
            a0 += sa.x * w0.x + sa.y * w0.y + sa.z * w0.z + sa.w * w0.w;
            a1 += sa.x * w1.x + sa.y * w1.y + sa.z * w1.z + sa.w * w1.w;
            a2v += sa.x * w2.x + sa.y * w2.y + sa.z * w2.z + sa.w * w2.w;
            a3 += sa.x * w3.x + sa.y * w3.y + sa.z * w3.z + sa.w * w3.w;
        }
        float4 o;
        o.x = (a0 > 20.f) ? a0 : log1pf(expf(a0));
        o.y = (a1 > 20.f) ? a1 : log1pf(expf(a1));
        o.z = (a2v > 20.f) ? a2v : log1pf(expf(a2v));
        o.w = (a3 > 20.f) ? a3 : log1pf(expf(a3));
        *(float4*)&g_delta[(size_t)(bm + m) * 512 + j] = o;
    }
}

// -------- chunked selective scan (round-10 exact): CTA per (b,d), 128 threads ------
__global__ void scan2_kernel(const float* __restrict__ alog, const float* __restrict__ dssm) {
    __shared__ float sh[128], sP[128];
    int bd = blockIdx.x;
    int b = bd >> 9, d = bd & 511;
    int tid = threadIdx.x;
    int c = tid >> 4, n = tid & 15;
    float Areg = -__expf(alog[d * 16 + n]);
    float Dd = dssm[d];
    const float* drow = g_delta + (size_t)(b * 1024) * 512 + d;
    const float* urow = g_xl + (size_t)(b * 1024) * 512 + d;
    const float* brow = g_xdbl + (size_t)(b * 1024) * 64 + 32 + n;
    const float* crow = g_xdbl + (size_t)(b * 1024) * 64 + 48 + n;
    const float* rrow = g_xr + (size_t)(b * 1024) * 1024 + 512 + d;
    float* yrow = g_y + (size_t)(b * 1024) * 512 + d;
    int lbase = c * 128;

    float h = 0.f, P = 1.f;
    for (int l0 = lbase; l0 < lbase + 128; l0 += 4) {
        float dv[4], uv[4], Bv[4], av[4];
        #pragma unroll
        for (int j = 0; j < 4; j++) {
            int l = l0 + j;
            dv[j] = drow[(size_t)l * 512];
            uv[j] = urow[(size_t)l * 512];
            Bv[j] = brow[(size_t)l * 64];
        }
        #pragma unroll
        for (int j = 0; j < 4; j++) av[j] = __expf(dv[j] * Areg);
        #pragma unroll
        for (int j = 0; j < 4; j++) {
            h = fmaf(av[j], h, dv[j] * Bv[j] * uv[j]);
            P *= av[j];
        }
    }
    sh[tid] = h;
    sP[tid] = P;
    __syncthreads();

    float h0 = 0.f;
    for (int cc = 0; cc < c; cc++)
        h0 = sh[cc * 16 + n] + sP[cc * 16 + n] * h0;

    h = h0;
    for (int l0 = lbase; l0 < lbase + 128; l0 += 4) {
        float dv[4], uv[4], Bv[4], Cv[4], av[4], p[4];
        #pragma unroll
        for (int j = 0; j < 4; j++) {
            int l = l0 + j;
            dv[j] = drow[(size_t)l * 512];
            uv[j] = urow[(size_t)l * 512];
            Bv[j] = brow[(size_t)l * 64];
            Cv[j] = crow[(size_t)l * 64];
        }
        #pragma unroll
        for (int j = 0; j < 4; j++) av[j] = __expf(dv[j] * Areg);
        #pragma unroll
        for (int j = 0; j < 4; j++) {
            h = fmaf(av[j], h, dv[j] * Bv[j] * uv[j]);
            p[j] = h * Cv[j];
        }
        #pragma unroll
        for (int st = 8; st > 0; st >>= 1) {
            #pragma unroll
            for (int j = 0; j < 4; j++)
                p[j] += __shfl_xor_sync(0xffffffffu, p[j], st);
        }
        if (n == 0) {
            #pragma unroll
            for (int j = 0; j < 4; j++) {
                int l = l0 + j;
                float r = rrow[(size_t)l * 1024];
                float sil = r / (1.f + __expf(-r));
                yrow[(size_t)l * 512] = (p[j] + uv[j] * Dd) * sil;
            }
        }
    }
}

// ---------------- LayerNorm(256) + residual into s (warp-shuffle) ----------------
__global__ void lnres_kernel(const float* __restrict__ yin, const float* __restrict__ g,
                             const float* __restrict__ bb) {
    int row = blockIdx.x;
    int c = threadIdx.x;
    __shared__ float ws1[8], ws2[8];
    float v = yin[row * 256 + c];
    float s1 = v;
    #pragma unroll
    for (int st = 16; st > 0; st >>= 1) s1 += __shfl_xor_sync(0xffffffffu, s1, st);
    if ((c & 31) == 0) ws1[c >> 5] = s1;
    __syncthreads();
    float tot = 0.f;
    #pragma unroll
    for (int k = 0; k < 8; k++) tot += ws1[k];
    float mean = tot * (1.f / 256.f);
    float dv = v - mean;
    float s2 = dv * dv;
    #pragma unroll
    for (int st = 16; st > 0; st >>= 1) s2 += __shfl_xor_sync(0xffffffffu, s2, st);
    if ((c & 31) == 0) ws2[c >> 5] = s2;
    __syncthreads();
    float var = 0.f;
    #pragma unroll
    for (int k = 0; k < 8; k++) var += ws2[k];
    var *= (1.f / 256.f);
    g_s[row * 256 + c] += dv * rsqrtf(var + EPSV) * g[c] + bb[c];
}

// ---------------- mean pool over L, two-stage ----------------
__global__ void pool_partial_kernel() {
    int b = blockIdx.x;
    int chunk = blockIdx.y;
    int c = threadIdx.x;
    float acc = 0.f;
    int l0 = chunk * 64;
    for (int l = l0; l < l0 + 64; l++) acc += g_s[(b * 1024 + l) * 256 + c];
    g_poolp[(b * 16 + chunk) * 256 + c] = acc;
}

// ---------------- head LN (reduces partials) ----------------
__global__ void headln_kernel(const float* __restrict__ nw, const float* __restrict__ nb) {
    int b = blockIdx.x;
    int c = threadIdx.x;
    __shared__ float red[256];
    float v = 0.f;
    #pragma unroll
    for (int k = 0; k < 16; k++) v += g_poolp[(b * 16 + k) * 256 + c];
    v *= (1.f / 1024.f);
    red[c] = v;
    __syncthreads();
    for (int st = 128; st > 0; st >>= 1) {
        if (c < st) red[c] += red[c + st];
        __syncthreads();
    }
    float mean = red[0] * (1.f / 256.f);
    __syncthreads();
    float dv = v - mean;
    red[c] = dv * dv;
    __syncthreads();
    for (int st = 128; st > 0; st >>= 1) {
        if (c < st) red[c] += red[c + st];
        __syncthreads();
    }
    float var = red[0] * (1.f / 256.f);
    g_pool[b * 256 + c] = dv * rsqrtf(var + EPSV) * nw[c] + nb[c];
}

// ---------------- fused FC + softmax ----------------
__global__ void fcsm_kernel(const float* __restrict__ fcw, const float* __restrict__ fcb,
                            float* __restrict__ out) {
    int b = blockIdx.x;
    int t = threadIdx.x;
    __shared__ float ps[256];
    __shared__ float lg[1000];
    __shared__ float red[256];
    ps[t] = g_pool[b * 256 + t];
    __syncthreads();
    for (int i = t; i < 1000; i += 256) {
        const float4* wp = (const float4*)(fcw + i * 256);
        float acc = fcb[i];
        #pragma unroll 8
        for (int k = 0; k < 64; k++) {
            float4 w4 = wp[k];
            float4 p4 = *(const float4*)&ps[k * 4];
            acc += w4.x * p4.x + w4.y * p4.y + w4.z * p4.z + w4.w * p4.w;
        }
        lg[i] = acc;
        out[b * 1000 + i] = acc;
    }
    __syncthreads();
    float mx = -1e30f;
    for (int i = t; i < 1000; i += 256) mx = fmaxf(mx, lg[i]);
    red[t] = mx;
    __syncthreads();
    for (int st = 128; st > 0; st >>= 1) {
        if (t < st) red[t] = fmaxf(red[t], red[t + st]);
        __syncthreads();
    }
    mx = red[0];
    __syncthreads();
    float sum = 0.f;
    for (int i = t; i < 1000; i += 256) sum += expf(lg[i] - mx);
    red[t] = sum;
    __syncthreads();
    for (int st = 128; st > 0; st >>= 1) {
        if (t < st) red[t] += red[t + st];
        __syncthreads();
    }
    float inv = 1.f / red[0];
    for (int i = t; i < 1000; i += 256)
        out[4000 + b * 1000 + i] = expf(lg[i] - mx) * inv;
}

// ---------------- host ----------------
template <int BM, int BN, int MODE>
static void launch_gemm7(const float* A, int lda, const float* W, const float* bias,
                         const float* bng, const float* bnb, float* C, int ldc,
                         int M, int N, int K, int act) {
    dim3 grid(N / BN, M / BM);
    gemm7_kernel<BM, BN, MODE><<<grid, 256>>>(A, lda, W, bias, bng, bnb, C, ldc, K, act);
}

extern "C" void kernel_launch(void* const* d_in, const int* in_sizes, int n_in,
                              void* d_out, int out_size) {
    const float* x    = (const float*)d_in[0];
    const float* c1w  = (const float*)d_in[1];
    const float* c1b  = (const float*)d_in[2];
    const float* g1   = (const float*)d_in[3];
    const float* b1   = (const float*)d_in[4];
    const float* c2w  = (const float*)d_in[5];
    const float* c2b  = (const float*)d_in[6];
    const float* g2   = (const float*)d_in[7];
    const float* b2   = (const float*)d_in[8];
    const float* pw   = (const float*)d_in[9];
    const float* pb   = (const float*)d_in[10];
    const float* g3   = (const float*)d_in[11];
    const float* b3   = (const float*)d_in[12];
    const float* ipw  = (const float*)d_in[13];
    const float* ipb  = (const float*)d_in[14];
    const float* cw   = (const float*)d_in[15];
    const float* cb   = (const float*)d_in[16];
    const float* xpw  = (const float*)d_in[17];
    const float* dpw  = (const float*)d_in[18];
    const float* dpb  = (const float*)d_in[19];
    const float* alog = (const float*)d_in[20];
    const float* dssm = (const float*)d_in[21];
    const float* opw  = (const float*)d_in[22];
    const float* opb  = (const float*)d_in[23];
    const float* lnw  = (const float*)d_in[24];
    const float* lnb  = (const float*)d_in[25];
    const float* nw   = (const float*)d_in[26];
    const float* nb   = (const float*)d_in[27];
    const float* fcw  = (const float*)d_in[28];
    const float* fcb  = (const float*)d_in[29];

    float *h1, *h2, *w2t, *w3t, *s, *xr, *xl, *y, *y2;
    cudaGetSymbolAddress((void**)&h1, g_h1);
    cudaGetSymbolAddress((void**)&h2, g_h2);
    cudaGetSymbolAddress((void**)&w2t, g_w2t);
    cudaGetSymbolAddress((void**)&w3t, g_w3t);
    cudaGetSymbolAddress((void**)&s, g_s);
    cudaGetSymbolAddress((void**)&xr, g_xr);
    cudaGetSymbolAddress((void**)&xl, g_xl);
    cudaGetSymbolAddress((void**)&y, g_y);
    cudaGetSymbolAddress((void**)&y2, g_y2);

    // stem (launch 1)
    stem_pre_kernel<<<10368, 256>>>(x, c1w, c1b, g1, b1, c2w, pw);
    launch_gemm7<128, 128, 1>(h1, 0, w2t, c2b, g2, b2, h2, 256, 16384, 256, 1152, 2);
    launch_gemm7<64, 128, 2>(h2, 0, w3t, pb, g3, b3, s, 256, 4096, 256, 1024, 2);

    // mamba blocks (launch 4 = in_proj of layer 0 -> profiled control)
    for (int i = 0; i < 4; i++) {
        launch_gemm7<128, 128, 0>(s, 256, ipw + i * 1024 * 256, ipb + i * 1024, 0, 0,
                                  xr, 1024, 4096, 1024, 256, 0);
        dwconv_kernel<<<2048, 256>>>(cw + i * 512 * 4, cb + i * 512);
        xdt_kernel<<<dim3(1, 64), 256>>>(xpw + i * 64 * 512, dpw + i * 512 * 32,
                                         dpb + i * 512);
        scan2_kernel<<<2048, 128>>>(alog + i * 512 * 16, dssm + i * 512);
        launch_gemm7<64, 128, 0>(y, 512, opw + i * 256 * 512, opb + i * 256, 0, 0,
                                 y2, 256, 4096, 256, 512, 0);
        lnres_kernel<<<4096, 256>>>(y2, lnw + i * 256, lnb + i * 256);
    }

    // head
    dim3 pgrid(4, 16);
    pool_partial_kernel<<<pgrid, 256>>>();
    headln_kernel<<<4, 256>>>(nw, nb);
    float* out = (float*)d_out;
    fcsm_kernel<<<4, 256>>>(fcw, fcb, out);
}

// round 15
// speedup vs baseline: 1.1088x; 1.1088x over previous
#include <cuda_runtime.h>
#include <math.h>

#define EPSV 1e-5f

typedef unsigned long long u64;

__device__ __forceinline__ u64 fma2(u64 a, u64 b, u64 c) {
    u64 d; asm("fma.rn.f32x2 %0, %1, %2, %3;" : "=l"(d) : "l"(a), "l"(b), "l"(c)); return d;
}
__device__ __forceinline__ u64 pack2(float lo, float hi) {
    u64 r; asm("mov.b64 %0, {%1, %2};" : "=l"(r) : "f"(lo), "f"(hi)); return r;
}
__device__ __forceinline__ void unpack2(u64 v, float& lo, float& hi) {
    asm("mov.b64 {%0, %1}, %2;" : "=f"(lo), "=f"(hi) : "l"(v));
}

// ---------------- scratch (no cudaMalloc allowed) ----------------
__device__ float g_h1[4 * 64 * 64 * 128];       // conv1 out, NHWC
__device__ float g_h2[4 * 64 * 64 * 256];       // conv2 out, NHWC
__device__ float g_w2t[256 * 9 * 128];          // c2w transposed [oc][r][ic]
__device__ float g_w3t[256 * 4 * 256];          // pw  transposed [oc][r][ic]
__device__ float g_s[4 * 1024 * 256];           // sequence
__device__ float g_xr[4 * 1024 * 1024];         // in_proj out (xi | res)
__device__ float g_xl[4 * 1024 * 512];          // after dw conv
__device__ float g_xdbl[4 * 1024 * 64];         // x_proj out (dt|B|C)
__device__ float g_delta[4 * 1024 * 512];
__device__ float g_y[4 * 1024 * 512];           // scan out * silu(res)
__device__ float g_y2[4 * 1024 * 256];          // out_proj out
__device__ float g_poolp[4 * 16 * 256];         // partial pool sums
__device__ float g_pool[4 * 256];

__device__ __forceinline__ float gelu_f(float x) {
    return 0.5f * x * (1.f + erff(x * 0.70710678118654752f));
}

// ---------------- fused: conv1 (NHWC out) + both weight transposes ----------------
__global__ void stem_pre_kernel(const float* __restrict__ x, const float* __restrict__ w,
                                const float* __restrict__ cb, const float* __restrict__ g,
                                const float* __restrict__ bb,
                                const float* __restrict__ c2w, const float* __restrict__ pw) {
    int bid = blockIdx.x;
    if (bid < 8192) {
        int idx = bid * 256 + threadIdx.x;
        int oc = idx & 127;
        int xo = (idx >> 7) & 63;
        int yo = (idx >> 13) & 63;
        int b  = idx >> 19;
        float acc = cb[oc];
        #pragma unroll
        for (int ic = 0; ic < 3; ic++) {
            #pragma unroll
            for (int ky = 0; ky < 3; ky++) {
                int iy = yo + ky - 1;
                if (iy < 0 || iy > 63) continue;
                #pragma unroll
                for (int kx = 0; kx < 3; kx++) {
                    int ix = xo + kx - 1;
                    if (ix < 0 || ix > 63) continue;
                    acc = fmaf(x[((b * 3 + ic) * 64 + iy) * 64 + ix],
                               w[((oc * 3 + ic) * 3 + ky) * 3 + kx], acc);
                }
            }
        }
        acc = acc * (g[oc] * rsqrtf(1.f + EPSV)) + bb[oc];
        g_h1[idx] = gelu_f(acc);
    } else if (bid < 8192 + 1152) {
        int idx = (bid - 8192) * 256 + threadIdx.x;
        int oc = idx / 1152;
        int rem = idx % 1152;
        int r = rem >> 7;
        int ic = rem & 127;
        g_w2t[idx] = c2w[(oc * 128 + ic) * 9 + r];
    } else {
        int idx = (bid - 9344) * 256 + threadIdx.x;
        int oc = idx >> 10;
        int rem = idx & 1023;
        int r = rem >> 8;
        int ic = rem & 255;
        g_w3t[idx] = pw[(oc * 256 + ic) * 4 + r];
    }
}

// ---------------- A-fragment gather for implicit-GEMM modes ----------------
template <int MODE>
__device__ __forceinline__ float4 gatherA(const float* __restrict__ src, int lda,
                                          int row, int k) {
    if (MODE == 0) {
        return *(const float4*)(src + (size_t)row * lda + k);
    } else if (MODE == 1) {
        int b = row >> 12, y = (row >> 6) & 63, x = row & 63;
        int r = k >> 7, ic = k & 127;
        int ky = (r * 11) >> 5;
        int kx = r - 3 * ky;
        int iy = y + ky - 1, ix = x + kx - 1;
        if (iy < 0 || iy > 63 || ix < 0 || ix > 63) return make_float4(0.f, 0.f, 0.f, 0.f);
        return *(const float4*)(src + ((((b << 6) + iy) << 6) + ix) * 128 + ic);
    } else {
        int b = row >> 10, oy = (row >> 5) & 31, ox = row & 31;
        int r = k >> 8, ic = k & 255;
        int iy = 2 * oy + (r >> 1), ix = 2 * ox + (r & 1);
        return *(const float4*)(src + ((((b << 6) + iy) << 6) + ix) * 256 + ic);
    }
}

// ------- warp-tiled SGEMM (round-10 exact): duplicated-A smem + u64 loads + FFMA2 --
template <int BM, int BN, int MODE>
__global__ void __launch_bounds__(256, 2)
gemm6_kernel(const float* __restrict__ A, int lda,
             const float* __restrict__ W,
             const float* __restrict__ bias,
             const float* __restrict__ bng,
             const float* __restrict__ bnb,
             float* __restrict__ C, int ldc,
             int K, int act) {
    constexpr int BK = 8;
    constexpr int TM = BM / 16;
    constexpr int TN = BN / 16;
    constexpr int QM = TM / 4;
    constexpr int QN = TN / 4;
    constexpr int TN2 = TN / 2;
    __shared__ __align__(16) float Asd[2][BK][2 * BM];
    __shared__ __align__(16) float Ws[2][BK][BN];
    int tid = threadIdx.x;
    int wid = tid >> 5, lane = tid & 31;
    int wm = wid >> 2, wn = wid & 3;
    int lm = lane >> 2, ln = lane & 3;
    int bm = blockIdx.y * BM, bn = blockIdx.x * BN;

    int aRow = tid >> 1;
    int aK = (tid & 1) * 4;
    bool aAct = aRow < BM;
    bool wAct = aRow < BN;
    int aGRow = bm + (aAct ? aRow : 0);
    const float* Wp = W + (size_t)(bn + (wAct ? aRow : 0)) * K + aK;

    float4 av = make_float4(0, 0, 0, 0), wv = make_float4(0, 0, 0, 0);
    if (aAct) av = gatherA<MODE>(A, lda, aGRow, aK);
    if (wAct) wv = *(const float4*)Wp;
    if (aAct) {
        *(float2*)&Asd[0][aK + 0][2 * aRow] = make_float2(av.x, av.x);
        *(float2*)&Asd[0][aK + 1][2 * aRow] = make_float2(av.y, av.y);
        *(float2*)&Asd[0][aK + 2][2 * aRow] = make_float2(av.z, av.z);
        *(float2*)&Asd[0][aK + 3][2 * aRow] = make_float2(av.w, av.w);
    }
    if (wAct) {
        Ws[0][aK + 0][aRow] = wv.x; Ws[0][aK + 1][aRow] = wv.y;
        Ws[0][aK + 2][aRow] = wv.z; Ws[0][aK + 3][aRow] = wv.w;
    }
    __syncthreads();

    u64 acc2[TM][TN2];
    #pragma unroll
    for (int i = 0; i < TM; i++)
        #pragma unroll
        for (int j = 0; j < TN2; j++) acc2[i][j] = pack2(0.f, 0.f);

    int nT = K / BK;
    for (int t = 0; t < nT; t++) {
        int buf = t & 1;
        if (t + 1 < nT) {
            if (aAct) av = gatherA<MODE>(A, lda, aGRow, (t + 1) * BK + aK);
            if (wAct) wv = *(const float4*)(Wp + (t + 1) * BK);
        }
        #pragma unroll
        for (int kk = 0; kk < BK; kk++) {
            u64 a2[TM], bp[TN2];
            #pragma unroll
            for (int q = 0; q < QM; q++)
                #pragma unroll
                for (int ii = 0; ii < 4; ii++)
                    a2[q * 4 + ii] = *(const u64*)
                        &Asd[buf][kk][2 * (wm * (BM / 2) + q * (BM / 4) + lm * 4 + ii)];
            #pragma unroll
            for (int q = 0; q < QN; q++)
                #pragma unroll
                for (int jj = 0; jj < 2; jj++)
                    bp[q * 2 + jj] = *(const u64*)
                        &Ws[buf][kk][wn * (BN / 4) + q * (BN / 8) + ln * 4 + 2 * jj];
            #pragma unroll
            for (int i = 0; i < TM; i++)
                #pragma unroll
                for (int j = 0; j < TN2; j++)
                    acc2[i][j] = fma2(a2[i], bp[j], acc2[i][j]);
        }
        if (t + 1 < nT) {
            int nb = buf ^ 1;
            if (aAct) {
                *(float2*)&Asd[nb][aK + 0][2 * aRow] = make_float2(av.x, av.x);
                *(float2*)&Asd[nb][aK + 1][2 * aRow] = make_float2(av.y, av.y);
                *(float2*)&Asd[nb][aK + 2][2 * aRow] = make_float2(av.z, av.z);
                *(float2*)&Asd[nb][aK + 3][2 * aRow] = make_float2(av.w, av.w);
            }
            if (wAct) {
                Ws[nb][aK + 0][aRow] = wv.x; Ws[nb][aK + 1][aRow] = wv.y;
                Ws[nb][aK + 2][aRow] = wv.z; Ws[nb][aK + 3][aRow] = wv.w;
            }
            __syncthreads();
        }
    }

    float acc[TM][TN];
    #pragma unroll
    for (int i = 0; i < TM; i++)
        #pragma unroll
        for (int j = 0; j < TN2; j++)
            unpack2(acc2[i][j], acc[i][2 * j], acc[i][2 * j + 1]);

    #pragma unroll
    for (int qn = 0; qn < QN; qn++) {
        int n0 = bn + wn * (BN / 4) + qn * (BN / 8) + ln * 4;
        float bj[4], gj[4], bbj[4];
        #pragma unroll
        for (int j = 0; j < 4; j++) {
            bj[j] = bias ? bias[n0 + j] : 0.f;
            if (act == 2) {
                gj[j] = bng[n0 + j] * rsqrtf(1.f + EPSV);
                bbj[j] = bnb[n0 + j];
            }
        }
        #pragma unroll
        for (int qm = 0; qm < QM; qm++) {
            #pragma unroll
            for (int i = 0; i < 4; i++) {
                int m = bm + wm * (BM / 2) + qm * (BM / 4) + lm * 4 + i;
                float4 o;
                float* op = (float*)&o;
                #pragma unroll
                for (int j = 0; j < 4; j++) {
                    float v = acc[qm * 4 + i][qn * 4 + j] + bj[j];
                    if (act == 1) v = (v > 20.f) ? v : log1pf(expf(v));
                    else if (act == 2) v = gelu_f(v * gj[j] + bbj[j]);
                    op[j] = v;
                }
                *(float4*)&C[(size_t)m * ldc + n0] = o;
            }
        }
    }
}

// ---------------- depthwise conv1d K=4, pad (1,2), vectorized x4 channels ----------
__global__ void dwconv_kernel(const float* __restrict__ cw, const float* __restrict__ cb) {
    int idx = blockIdx.x * blockDim.x + threadIdx.x;
    if (idx >= 4 * 1024 * 128) return;
    int d4 = idx & 127;
    int d = d4 << 2;
    int l = (idx >> 7) & 1023;
    int b = idx >> 17;
    float4 acc = *(const float4*)&cb[d];
    float4 w0 = *(const float4*)&cw[(d + 0) * 4];
    float4 w1 = *(const float4*)&cw[(d + 1) * 4];
    float4 w2 = *(const float4*)&cw[(d + 2) * 4];
    float4 w3 = *(const float4*)&cw[(d + 3) * 4];
    const float* wp0 = (const float*)&w0;
    const float* wp1 = (const float*)&w1;
    const float* wp2 = (const float*)&w2;
    const float* wp3 = (const float*)&w3;
    #pragma unroll
    for (int k = 0; k < 4; k++) {
        int l2 = l - 1 + k;
        if (l2 >= 0 && l2 < 1024) {
            float4 xv = *(const float4*)&g_xr[(size_t)(b * 1024 + l2) * 1024 + d];
            acc.x = fmaf(wp0[k], xv.x, acc.x);
            acc.y = fmaf(wp1[k], xv.y, acc.y);
            acc.z = fmaf(wp2[k], xv.z, acc.z);
            acc.w = fmaf(wp3[k], xv.w, acc.w);
        }
    }
    *(float4*)&g_xl[(size_t)(b * 1024 + l) * 512 + d] = acc;
}

// --------- fused x_proj (64x64x512 GEMM) + dt_proj (K=32 GEMM) + softplus ----------
__global__ void __launch_bounds__(256, 2)
xdt_kernel(const float* __restrict__ xpw, const float* __restrict__ dpw,
           const float* __restrict__ dpb) {
    constexpr int BK = 8;
    __shared__ __align__(16) float Asd[2][BK][2 * 64];
    __shared__ __align__(16) float Ws[2][BK][64];
    __shared__ __align__(16) float sdt[64][36];
    int tid = threadIdx.x;
    int wid = tid >> 5, lane = tid & 31;
    int wm = wid >> 2, wn = wid & 3;
    int lm = lane >> 2, ln = lane & 3;
    int bm = blockIdx.y * 64;

    int aRow = tid >> 1;
    int aK = (tid & 1) * 4;
    bool act8 = aRow < 64;
    const float* Ap = g_xl + (size_t)(bm + (act8 ? aRow : 0)) * 512 + aK;
    const float* Wp = xpw + (size_t)(act8 ? aRow : 0) * 512 + aK;

    float4 av = make_float4(0, 0, 0, 0), wv = make_float4(0, 0, 0, 0);
    if (act8) { av = *(const float4*)Ap; wv = *(const float4*)Wp; }
    if (act8) {
        *(float2*)&Asd[0][aK + 0][2 * aRow] = make_float2(av.x, av.x);
        *(float2*)&Asd[0][aK + 1][2 * aRow] = make_float2(av.y, av.y);
        *(float2*)&Asd[0][aK + 2][2 * aRow] = make_float2(av.z, av.z);
        *(float2*)&Asd[0][aK + 3][2 * aRow] = make_float2(av.w, av.w);
        Ws[0][aK + 0][aRow] = wv.x; Ws[0][aK + 1][aRow] = wv.y;
        Ws[0][aK + 2][aRow] = wv.z; Ws[0][aK + 3][aRow] = wv.w;
    }
    __syncthreads();

    u64 acc2[4][2];
    #pragma unroll
    for (int i = 0; i < 4; i++)
        #pragma unroll
        for (int j = 0; j < 2; j++) acc2[i][j] = pack2(0.f, 0.f);

    for (int t = 0; t < 64; t++) {
        int buf = t & 1;
        if (t + 1 < 64 && act8) {
            av = *(const float4*)(Ap + (t + 1) * BK);
            wv = *(const float4*)(Wp + (t + 1) * BK);
        }
        #pragma unroll
        for (int kk = 0; kk < BK; kk++) {
            u64 a2[4], bp[2];
            #pragma unroll
            for (int ii = 0; ii < 4; ii++)
                a2[ii] = *(const u64*)&Asd[buf][kk][2 * (wm * 32 + lm * 4 + ii)];
            #pragma unroll
            for (int jj = 0; jj < 2; jj++)
                bp[jj] = *(const u64*)&Ws[buf][kk][wn * 16 + ln * 4 + 2 * jj];
            #pragma unroll
            for (int i = 0; i < 4; i++)
                #pragma unroll
                for (int j = 0; j < 2; j++)
                    acc2[i][j] = fma2(a2[i], bp[j], acc2[i][j]);
        }
        if (t + 1 < 64 && act8) {
            int nb = buf ^ 1;
            *(float2*)&Asd[nb][aK + 0][2 * aRow] = make_float2(av.x, av.x);
            *(float2*)&Asd[nb][aK + 1][2 * aRow] = make_float2(av.y, av.y);
            *(float2*)&Asd[nb][aK + 2][2 * aRow] = make_float2(av.z, av.z);
            *(float2*)&Asd[nb][aK + 3][2 * aRow] = make_float2(av.w, av.w);
            Ws[nb][aK + 0][aRow] = wv.x; Ws[nb][aK + 1][aRow] = wv.y;
            Ws[nb][aK + 2][aRow] = wv.z; Ws[nb][aK + 3][aRow] = wv.w;
        }
        __syncthreads();
    }

    int n0 = wn * 16 + ln * 4;
    #pragma unroll
    for (int i = 0; i < 4; i++) {
        int m = wm * 32 + lm * 4 + i;
        float v0, v1, v2, v3;
        unpack2(acc2[i][0], v0, v1);
        unpack2(acc2[i][1], v2, v3);
        float4 o = make_float4(v0, v1, v2, v3);
        *(float4*)&g_xdbl[(size_t)(bm + m) * 64 + n0] = o;
        if (n0 < 32) {
            sdt[m][n0 + 0] = v0; sdt[m][n0 + 1] = v1;
            sdt[m][n0 + 2] = v2; sdt[m][n0 + 3] = v3;
        }
    }
    __syncthreads();

    int m = tid >> 2;
    int j0 = (tid & 3) * 4;
    for (int it = 0; it < 32; it++) {
        int j = j0 + it * 16;
        float a0 = dpb[j + 0], a1 = dpb[j + 1], a2v = dpb[j + 2], a3 = dpb[j + 3];
        #pragma unroll
        for (int k4 = 0; k4 < 8; k4++) {
            float4 sa = *(const float4*)&sdt[m][k4 * 4];
            float4 w0 = *(const float4*)&dpw[(j + 0) * 32 + k4 * 4];
            float4 w1 = *(const float4*)&dpw[(j + 1) * 32 + k4 * 4];
            float4 w2 = *(const float4*)&dpw[(j + 2) * 32 + k4 * 4];
            float4 w3 = *(const float4*)&dpw[(j + 3) * 32 + k4 * 4];
            a0 += sa.x * w0.x + sa.y * w0.y + sa.z * w0.z + sa.w * w0.w;
            a1 += sa.x * w1.x + sa.y * w1.y + sa.z * w1.z + sa.w * w1.w;
            a2v += sa.x * w2.x + sa.y * w2.y + sa.z * w2.z + sa.w * w2.w;
            a3 += sa.x * w3.x + sa.y * w3.y + sa.z * w3.z + sa.w * w3.w;
        }
        float4 o;
        o.x = (a0 > 20.f) ? a0 : log1pf(expf(a0));
        o.y = (a1 > 20.f) ? a1 : log1pf(expf(a1));
        o.z = (a2v > 20.f) ? a2v : log1pf(expf(a2v));
        o.w = (a3 > 20.f) ? a3 : log1pf(expf(a3));
        *(float4*)&g_delta[(size_t)(bm + m) * 512 + j] = o;
    }
}

// ----- chunked selective scan v3: CTA per (b,d), 256 threads = 16 chunks x 16 n ----
// chunk = 64 steps; phase1 local scan + P; smem combine (<=15 serial); phase2 emit
__global__ void __launch_bounds__(256)
scan3_kernel(const float* __restrict__ alog, const float* __restrict__ dssm) {
    __shared__ float sh[256], sP[256];
    int bd = blockIdx.x;
    int b = bd >> 9, d = bd & 511;
    int tid = threadIdx.x;
    int c = tid >> 4, n = tid & 15;
    float Areg = -__expf(alog[d * 16 + n]);
    float Dd = dssm[d];
    const float* drow = g_delta + (size_t)(b * 1024) * 512 + d;
    const float* urow = g_xl + (size_t)(b * 1024) * 512 + d;
    const float* brow = g_xdbl + (size_t)(b * 1024) * 64 + 32 + n;
    const float* crow = g_xdbl + (size_t)(b * 1024) * 64 + 48 + n;
    const float* rrow = g_xr + (size_t)(b * 1024) * 1024 + 512 + d;
    float* yrow = g_y + (size_t)(b * 1024) * 512 + d;
    int lbase = c * 64;

    // phase 1: local scan with h0 = 0 over 64 steps, track P = prod(a)
    float h = 0.f, P = 1.f;
    for (int l0 = lbase; l0 < lbase + 64; l0 += 4) {
        float dv[4], uv[4], Bv[4], av[4];
        #pragma unroll
        for (int j = 0; j < 4; j++) {
            int l = l0 + j;
            dv[j] = drow[(size_t)l * 512];
            uv[j] = urow[(size_t)l * 512];
            Bv[j] = brow[(size_t)l * 64];
        }
        #pragma unroll
        for (int j = 0; j < 4; j++) av[j] = __expf(dv[j] * Areg);
        #pragma unroll
        for (int j = 0; j < 4; j++) {
            h = fmaf(av[j], h, dv[j] * Bv[j] * uv[j]);
            P *= av[j];
        }
    }
    sh[tid] = h;
    sP[tid] = P;
    __syncthreads();

    // chunk-start state: serial combine over preceding chunks (exact recurrence)
    float h0 = 0.f;
    for (int cc = 0; cc < c; cc++)
        h0 = sh[cc * 16 + n] + sP[cc * 16 + n] * h0;

    // phase 2: rescan chunk from h0, emit y
    h = h0;
    for (int l0 = lbase; l0 < lbase + 64; l0 += 4) {
        float dv[4], uv[4], Bv[4], Cv[4], av[4], p[4];
        #pragma unroll
        for (int j = 0; j < 4; j++) {
            int l = l0 + j;
            dv[j] = drow[(size_t)l * 512];
            uv[j] = urow[(size_t)l * 512];
            Bv[j] = brow[(size_t)l * 64];
            Cv[j] = crow[(size_t)l * 64];
        }
        #pragma unroll
        for (int j = 0; j < 4; j++) av[j] = __expf(dv[j] * Areg);
        #pragma unroll
        for (int j = 0; j < 4; j++) {
            h = fmaf(av[j], h, dv[j] * Bv[j] * uv[j]);
            p[j] = h * Cv[j];
        }
        #pragma unroll
        for (int st = 8; st > 0; st >>= 1) {
            #pragma unroll
            for (int j = 0; j < 4; j++)
                p[j] += __shfl_xor_sync(0xffffffffu, p[j], st);
        }
        if (n == 0) {
            #pragma unroll
            for (int j = 0; j < 4; j++) {
                int l = l0 + j;
                float r = rrow[(size_t)l * 1024];
                float sil = r / (1.f + __expf(-r));
                yrow[(size_t)l * 512] = (p[j] + uv[j] * Dd) * sil;
            }
        }
    }
}

// ---------------- LayerNorm(256) + residual into s (warp-shuffle) ----------------
__global__ void lnres_kernel(const float* __restrict__ yin, const float* __restrict__ g,
                             const float* __restrict__ bb) {
    int row = blockIdx.x;
    int c = threadIdx.x;
    __shared__ float ws1[8], ws2[8];
    float v = yin[row * 256 + c];
    float s1 = v;
    #pragma unroll
    for (int st = 16; st > 0; st >>= 1) s1 += __shfl_xor_sync(0xffffffffu, s1, st);
    if ((c & 31) == 0) ws1[c >> 5] = s1;
    __syncthreads();
    float tot = 0.f;
    #pragma unroll
    for (int k = 0; k < 8; k++) tot += ws1[k];
    float mean = tot * (1.f / 256.f);
    float dv = v - mean;
    float s2 = dv * dv;
    #pragma unroll
    for (int st = 16; st > 0; st >>= 1) s2 += __shfl_xor_sync(0xffffffffu, s2, st);
    if ((c & 31) == 0) ws2[c >> 5] = s2;
    __syncthreads();
    float var = 0.f;
    #pragma unroll
    for (int k = 0; k < 8; k++) var += ws2[k];
    var *= (1.f / 256.f);
    g_s[row * 256 + c] += dv * rsqrtf(var + EPSV) * g[c] + bb[c];
}

// ---------------- mean pool over L, two-stage ----------------
__global__ void pool_partial_kernel() {
    int b = blockIdx.x;
    int chunk = blockIdx.y;
    int c = threadIdx.x;
    float acc = 0.f;
    int l0 = chunk * 64;
    for (int l = l0; l < l0 + 64; l++) acc += g_s[(b * 1024 + l) * 256 + c];
    g_poolp[(b * 16 + chunk) * 256 + c] = acc;
}

// ---------------- head LN (reduces partials) ----------------
__global__ void headln_kernel(const float* __restrict__ nw, const float* __restrict__ nb) {
    int b = blockIdx.x;
    int c = threadIdx.x;
    __shared__ float red[256];
    float v = 0.f;
    #pragma unroll
    for (int k = 0; k < 16; k++) v += g_poolp[(b * 16 + k) * 256 + c];
    v *= (1.f / 1024.f);
    red[c] = v;
    __syncthreads();
    for (int st = 128; st > 0; st >>= 1) {
        if (c < st) red[c] += red[c + st];
        __syncthreads();
    }
    float mean = red[0] * (1.f / 256.f);
    __syncthreads();
    float dv = v - mean;
    red[c] = dv * dv;
    __syncthreads();
    for (int st = 128; st > 0; st >>= 1) {
        if (c < st) red[c] += red[c + st];
        __syncthreads();
    }
    float var = red[0] * (1.f / 256.f);
    g_pool[b * 256 + c] = dv * rsqrtf(var + EPSV) * nw[c] + nb[c];
}

// ---------------- fused FC + softmax ----------------
__global__ void fcsm_kernel(const float* __restrict__ fcw, const float* __restrict__ fcb,
                            float* __restrict__ out) {
    int b = blockIdx.x;
    int t = threadIdx.x;
    __shared__ float ps[256];
    __shared__ float lg[1000];
    __shared__ float red[256];
    ps[t] = g_pool[b * 256 + t];
    __syncthreads();
    for (int i = t; i < 1000; i += 256) {
        const float4* wp = (const float4*)(fcw + i * 256);
        float acc = fcb[i];
        #pragma unroll 8
        for (int k = 0; k < 64; k++) {
            float4 w4 = wp[k];
            float4 p4 = *(const float4*)&ps[k * 4];
            acc += w4.x * p4.x + w4.y * p4.y + w4.z * p4.z + w4.w * p4.w;
        }
        lg[i] = acc;
        out[b * 1000 + i] = acc;
    }
    __syncthreads();
    float mx = -1e30f;
    for (int i = t; i < 1000; i += 256) mx = fmaxf(mx, lg[i]);
    red[t] = mx;
    __syncthreads();
    for (int st = 128; st > 0; st >>= 1) {
        if (t < st) red[t] = fmaxf(red[t], red[t + st]);
        __syncthreads();
    }
    mx = red[0];
    __syncthreads();
    float sum = 0.f;
    for (int i = t; i < 1000; i += 256) sum += expf(lg[i] - mx);
    red[t] = sum;
    __syncthreads();
    for (int st = 128; st > 0; st >>= 1) {
        if (t < st) red[t] += red[t + st];
        __syncthreads();
    }
    float inv = 1.f / red[0];
    for (int i = t; i < 1000; i += 256)
        out[4000 + b * 1000 + i] = expf(lg[i] - mx) * inv;
}

// ---------------- host ----------------
template <int BM, int BN, int MODE>
static void launch_gemm6(const float* A, int lda, const float* W, const float* bias,
                         const float* bng, const float* bnb, float* C, int ldc,
                         int M, int N, int K, int act) {
    dim3 grid(N / BN, M / BM);
    gemm6_kernel<BM, BN, MODE><<<grid, 256>>>(A, lda, W, bias, bng, bnb, C, ldc, K, act);
}

extern "C" void kernel_launch(void* const* d_in, const int* in_sizes, int n_in,
                              void* d_out, int out_size) {
    const float* x    = (const float*)d_in[0];
    const float* c1w  = (const float*)d_in[1];
    const float* c1b  = (const float*)d_in[2];
    const float* g1   = (const float*)d_in[3];
    const float* b1   = (const float*)d_in[4];
    const float* c2w  = (const float*)d_in[5];
    const float* c2b  = (const float*)d_in[6];
    const float* g2   = (const float*)d_in[7];
    const float* b2   = (const float*)d_in[8];
    const float* pw   = (const float*)d_in[9];
    const float* pb   = (const float*)d_in[10];
    const float* g3   = (const float*)d_in[11];
    const float* b3   = (const float*)d_in[12];
    const float* ipw  = (const float*)d_in[13];
    const float* ipb  = (const float*)d_in[14];
    const float* cw   = (const float*)d_in[15];
    const float* cb   = (const float*)d_in[16];
    const float* xpw  = (const float*)d_in[17];
    const float* dpw  = (const float*)d_in[18];
    const float* dpb  = (const float*)d_in[19];
    const float* alog = (const float*)d_in[20];
    const float* dssm = (const float*)d_in[21];
    const float* opw  = (const float*)d_in[22];
    const float* opb  = (const float*)d_in[23];
    const float* lnw  = (const float*)d_in[24];
    const float* lnb  = (const float*)d_in[25];
    const float* nw   = (const float*)d_in[26];
    const float* nb   = (const float*)d_in[27];
    const float* fcw  = (const float*)d_in[28];
    const float* fcb  = (const float*)d_in[29];

    float *h1, *h2, *w2t, *w3t, *s, *xr, *xl, *y, *y2;
    cudaGetSymbolAddress((void**)&h1, g_h1);
    cudaGetSymbolAddress((void**)&h2, g_h2);
    cudaGetSymbolAddress((void**)&w2t, g_w2t);
    cudaGetSymbolAddress((void**)&w3t, g_w3t);
    cudaGetSymbolAddress((void**)&s, g_s);
    cudaGetSymbolAddress((void**)&xr, g_xr);
    cudaGetSymbolAddress((void**)&xl, g_xl);
    cudaGetSymbolAddress((void**)&y, g_y);
    cudaGetSymbolAddress((void**)&y2, g_y2);

    // stem
    stem_pre_kernel<<<10368, 256>>>(x, c1w, c1b, g1, b1, c2w, pw);
    launch_gemm6<128, 128, 1>(h1, 0, w2t, c2b, g2, b2, h2, 256, 16384, 256, 1152, 2);
    launch_gemm6<64, 128, 2>(h2, 0, w3t, pb, g3, b3, s, 256, 4096, 256, 1024, 2);

    // mamba blocks (launch 4 = in_proj of layer 0 -> profiled control)
    for (int i = 0; i < 4; i++) {
        launch_gemm6<128, 128, 0>(s, 256, ipw + i * 1024 * 256, ipb + i * 1024, 0, 0,
                                  xr, 1024, 4096, 1024, 256, 0);
        dwconv_kernel<<<2048, 256>>>(cw + i * 512 * 4, cb + i * 512);
        xdt_kernel<<<dim3(1, 64), 256>>>(xpw + i * 64 * 512, dpw + i * 512 * 32,
                                         dpb + i * 512);
        scan3_kernel<<<2048, 256>>>(alog + i * 512 * 16, dssm + i * 512);
        launch_gemm6<64, 128, 0>(y, 512, opw + i * 256 * 512, opb + i * 256, 0, 0,
                                 y2, 256, 4096, 256, 512, 0);
        lnres_kernel<<<4096, 256>>>(y2, lnw + i * 256, lnb + i * 256);
    }

    // head
    dim3 pgrid(4, 16);
    pool_partial_kernel<<<pgrid, 256>>>();
    headln_kernel<<<4, 256>>>(nw, nb);
    float* out = (float*)d_out;
    fcsm_kernel<<<4, 256>>>(fcw, fcb, out);
}